// round 14
// baseline (speedup 1.0000x reference)
#include <cuda_runtime.h>
#include <cstdint>

// ===========================================================================
// MHA B=2,S=2048,E=1024,H=16,D=64 fp32.  SIMT f32x2 everywhere.
//  - GEMMs: R5 engine + launch_bounds(256,2) (measured 562us proj, 190us out).
//  - attention: R5 thread mapping (1 row/thread, BQ=128, 128 thr, NO reg cap)
//    with K-PACKED scores: sacc[j] accumulates (even-d, odd-d) partial sums,
//    horizontal-add at softmax. K stays row-major (no transpose, float4
//    loads), q pairs read directly as ull2 from stride-68 Qs (no pk2 dups).
//  Reg caps <200 proven to spill (R9/R12); pair/key-split proven worse.
// ===========================================================================

typedef unsigned long long ull;
#define DI __device__ __forceinline__

DI ull pk2(float lo, float hi) {
    ull r; asm("mov.b64 %0, {%1,%2};" : "=l"(r) : "f"(lo), "f"(hi)); return r;
}
DI void upk2(ull v, float& lo, float& hi) {
    asm("mov.b64 {%0,%1}, %2;" : "=f"(lo), "=f"(hi) : "l"(v));
}
DI ull ffma2(ull a, ull b, ull c) {
    ull d; asm("fma.rn.f32x2 %0, %1, %2, %3;" : "=l"(d) : "l"(a), "l"(b), "l"(c)); return d;
}
DI ull fmul2(ull a, ull b) {
    ull d; asm("mul.rn.f32x2 %0, %1, %2;" : "=l"(d) : "l"(a), "l"(b)); return d;
}

constexpr int B = 2, S = 2048, E = 1024, H = 16, D = 64;

__device__ float g_q[B * H * S * D];
__device__ float g_k[B * H * S * D];
__device__ float g_v[B * H * S * D];
__device__ float g_att[B * S * E];

// ---------------------------------------------------------------------------
// R5 GEMM engine with launch_bounds(256,2) (measured best).
// ---------------------------------------------------------------------------
template <int MODE>
DI void gemm_body(const float* __restrict__ X, const float* __restrict__ W,
                  const float* __restrict__ bias, float* __restrict__ out)
{
    __shared__ __align__(16) float As[8][132];
    __shared__ __align__(16) float Ws[8][132];

    const int tid = threadIdx.x;
    const int tx = tid & 15, ty = tid >> 4;
    const int m0 = blockIdx.y * 128;
    const int n0 = blockIdx.x * 128;
    const int lr = tid >> 1;
    const int lc = (tid & 1) << 2;

    const float* Xp = X + (size_t)(m0 + lr) * 1024 + lc;
    const float* Wp = W + (size_t)(n0 + lr) * 1024 + lc;

    ull acc[8][4];
#pragma unroll
    for (int i = 0; i < 8; i++)
#pragma unroll
        for (int j = 0; j < 4; j++) acc[i][j] = 0ull;

    float4 av = *(const float4*)Xp;
    float4 wv = *(const float4*)Wp;

    for (int k0 = 0; k0 < 1024; k0 += 8) {
        __syncthreads();
        As[lc + 0][lr] = av.x; As[lc + 1][lr] = av.y;
        As[lc + 2][lr] = av.z; As[lc + 3][lr] = av.w;
        Ws[lc + 0][lr] = wv.x; Ws[lc + 1][lr] = wv.y;
        Ws[lc + 2][lr] = wv.z; Ws[lc + 3][lr] = wv.w;
        __syncthreads();
        if (k0 + 8 < 1024) {
            av = *(const float4*)(Xp + k0 + 8);
            wv = *(const float4*)(Wp + k0 + 8);
        }
#pragma unroll
        for (int kk = 0; kk < 8; kk++) {
            float4 a0 = *(const float4*)&As[kk][ty * 4];
            float4 a1 = *(const float4*)&As[kk][64 + ty * 4];
            ulonglong2 b0 = *(const ulonglong2*)&Ws[kk][tx * 4];
            ulonglong2 b1 = *(const ulonglong2*)&Ws[kk][64 + tx * 4];
            float a[8] = {a0.x, a0.y, a0.z, a0.w, a1.x, a1.y, a1.z, a1.w};
            ull bv[4] = {b0.x, b0.y, b1.x, b1.y};
#pragma unroll
            for (int i = 0; i < 8; i++) {
                ull a2 = pk2(a[i], a[i]);
#pragma unroll
                for (int j = 0; j < 4; j++) acc[i][j] = ffma2(a2, bv[j], acc[i][j]);
            }
        }
    }

    float4 bias0 = *(const float4*)&bias[n0 + tx * 4];
    float4 bias1 = *(const float4*)&bias[n0 + 64 + tx * 4];

#pragma unroll
    for (int i = 0; i < 8; i++) {
        int m = m0 + (i >> 2) * 64 + ty * 4 + (i & 3);
        float4 r0, r1;
        upk2(acc[i][0], r0.x, r0.y); upk2(acc[i][1], r0.z, r0.w);
        upk2(acc[i][2], r1.x, r1.y); upk2(acc[i][3], r1.z, r1.w);
        r0.x += bias0.x; r0.y += bias0.y; r0.z += bias0.z; r0.w += bias0.w;
        r1.x += bias1.x; r1.y += bias1.y; r1.z += bias1.z; r1.w += bias1.w;
        if (MODE == 0) {
            int bb = m >> 11, ss = m & 2047;
            int nA = n0 + tx * 4;
            int nB = n0 + 64 + tx * 4;
            int hA = nA >> 6, dA = nA & 63;
            int hB = nB >> 6, dB = nB & 63;
            *(float4*)&out[((size_t)(bb * H + hA) * S + ss) * D + dA] = r0;
            *(float4*)&out[((size_t)(bb * H + hB) * S + ss) * D + dB] = r1;
        } else {
            *(float4*)&out[(size_t)m * 1024 + n0 + tx * 4] = r0;
            *(float4*)&out[(size_t)m * 1024 + n0 + 64 + tx * 4] = r1;
        }
    }
}

__global__ __launch_bounds__(256, 2) void gemm_proj(const float* __restrict__ xq,
                                                    const float* __restrict__ xk,
                                                    const float* __restrict__ xv,
                                                    const float* __restrict__ Wq,
                                                    const float* __restrict__ Wk,
                                                    const float* __restrict__ Wv,
                                                    const float* __restrict__ bq,
                                                    const float* __restrict__ bk,
                                                    const float* __restrict__ bv,
                                                    float* __restrict__ oq,
                                                    float* __restrict__ ok,
                                                    float* __restrict__ ov)
{
    const int z = blockIdx.z;
    const float* X = (z == 0) ? xq : (z == 1) ? xk : xv;
    const float* W = (z == 0) ? Wq : (z == 1) ? Wk : Wv;
    const float* bb = (z == 0) ? bq : (z == 1) ? bk : bv;
    float* out = (z == 0) ? oq : (z == 1) ? ok : ov;
    gemm_body<0>(X, W, bb, out);
}

__global__ __launch_bounds__(256, 2) void gemm_out(const float* __restrict__ X,
                                                   const float* __restrict__ W,
                                                   const float* __restrict__ bias,
                                                   float* __restrict__ out)
{
    gemm_body<1>(X, W, bias, out);
}

// ---------------------------------------------------------------------------
// Flash attention, k-packed scores.
// BQ=128 rows/CTA, 128 threads, 1 row/thread, NO launch bounds (reg caps
// proven to spill). Q smem stride 68 (aligned ull2 reads, conflict-free per
// LDS.128 quad-phase). K and V both row-major [j][64] (broadcast reads).
// Scores: sacc[j] = packed (even-d, odd-d) partial dot; horizontal add at
// softmax. PV identical to R5 (pairs over d, pk2-dup p).
// ---------------------------------------------------------------------------
constexpr int BQ = 128, TK = 64;
constexpr int QSTR = 68;
constexpr int ATTN_SMEM = (BQ * QSTR + TK * D + TK * D) * 4;  // 67584

__global__ __launch_bounds__(128) void attn_kernel(const float* __restrict__ Q,
                                                   const float* __restrict__ K,
                                                   const float* __restrict__ V,
                                                   float* __restrict__ Oout)
{
    extern __shared__ float sm[];
    float* Qs = sm;                   // [128][68]
    float* Ks = sm + BQ * QSTR;       // [64][64]
    float* Vs = Ks + TK * D;          // [64][64]

    const int t  = threadIdx.x;
    const int bh = blockIdx.y;
    const int q0 = blockIdx.x * BQ;
    const float* Qb = Q + (size_t)bh * (S * D);
    const float* Kb = K + (size_t)bh * (S * D);
    const float* Vb = V + (size_t)bh * (S * D);

    // load Q tile scaled (float4 LDG -> float4 STS, stride 68)
#pragma unroll
    for (int i = 0; i < 16; i++) {
        int idx = i * 128 + t;            // 0..2047 float4s
        int r = idx >> 4, c4 = idx & 15;
        float4 v = *(const float4*)&Qb[(size_t)(q0 + r) * D + c4 * 4];
        float4 s = { v.x * 0.125f, v.y * 0.125f, v.z * 0.125f, v.w * 0.125f };
        *(float4*)&Qs[r * QSTR + c4 * 4] = s;
    }

    ull o2[32];
#pragma unroll
    for (int i = 0; i < 32; i++) o2[i] = 0ull;
    float m_run = -3.0e38f, l_run = 0.0f;

    const float* qrow = &Qs[t * QSTR];

    for (int kt = 0; kt < S; kt += TK) {
        __syncthreads();
        // K and V tiles: pure float4 copies (row-major, no transpose)
#pragma unroll
        for (int i = 0; i < 8; i++) {
            int idx = i * 128 + t;            // 0..1023 float4s
            int j = idx >> 4, d4 = idx & 15;
            *(float4*)&Ks[j * D + d4 * 4] =
                *(const float4*)&Kb[(size_t)(kt + j) * D + d4 * 4];
            *(float4*)&Vs[j * D + d4 * 4] =
                *(const float4*)&Vb[(size_t)(kt + j) * D + d4 * 4];
        }
        __syncthreads();

#pragma unroll
        for (int g = 0; g < 4; g++) {
            // --- scores: packed along d ---
            ull sacc[16];
#pragma unroll
            for (int i = 0; i < 16; i++) sacc[i] = 0ull;

#pragma unroll
            for (int dc = 0; dc < D; dc += 16) {
                ulonglong2 qu0 = *(const ulonglong2*)&qrow[dc];
                ulonglong2 qu1 = *(const ulonglong2*)&qrow[dc + 4];
                ulonglong2 qu2 = *(const ulonglong2*)&qrow[dc + 8];
                ulonglong2 qu3 = *(const ulonglong2*)&qrow[dc + 12];
                ull q2[8] = { qu0.x, qu0.y, qu1.x, qu1.y,
                              qu2.x, qu2.y, qu3.x, qu3.y };
#pragma unroll
                for (int j2 = 0; j2 < 16; j2++) {
                    const float* krow = &Ks[(g * 16 + j2) * D + dc];
                    ulonglong2 k0 = *(const ulonglong2*)&krow[0];
                    ulonglong2 k1 = *(const ulonglong2*)&krow[4];
                    ulonglong2 k2 = *(const ulonglong2*)&krow[8];
                    ulonglong2 k3 = *(const ulonglong2*)&krow[12];
                    ull a = sacc[j2];
                    a = ffma2(q2[0], k0.x, a);
                    a = ffma2(q2[1], k0.y, a);
                    a = ffma2(q2[2], k1.x, a);
                    a = ffma2(q2[3], k1.y, a);
                    a = ffma2(q2[4], k2.x, a);
                    a = ffma2(q2[5], k2.y, a);
                    a = ffma2(q2[6], k3.x, a);
                    a = ffma2(q2[7], k3.y, a);
                    sacc[j2] = a;
                }
            }

            // horizontal add -> 16 scalar scores
            float s[16];
#pragma unroll
            for (int i = 0; i < 16; i++) {
                float x, y; upk2(sacc[i], x, y);
                s[i] = x + y;
            }

            // online softmax
            float gmax = -3.0e38f;
#pragma unroll
            for (int i = 0; i < 16; i++) gmax = fmaxf(gmax, s[i]);
            if (__any_sync(0xffffffffu, gmax > m_run)) {
                float mnew = fmaxf(m_run, gmax);
                float alpha = __expf(m_run - mnew);
                l_run *= alpha;
                ull al2 = pk2(alpha, alpha);
#pragma unroll
                for (int i = 0; i < 32; i++) o2[i] = fmul2(o2[i], al2);
                m_run = mnew;
            }
            float lsum = 0.0f;
#pragma unroll
            for (int i = 0; i < 16; i++) {
                s[i] = __expf(s[i] - m_run);
                lsum += s[i];
            }
            l_run += lsum;

            // --- PV (as R5): pairs over d, p dup'd via pk2 ---
#pragma unroll
            for (int j2 = 0; j2 < 8; j2++) {
                int j = g * 16 + 2 * j2;
                ull pa = pk2(s[2 * j2], s[2 * j2]);
                ull pb = pk2(s[2 * j2 + 1], s[2 * j2 + 1]);
                const ulonglong2* v0 = (const ulonglong2*)&Vs[j * D];
                const ulonglong2* v1 = (const ulonglong2*)&Vs[(j + 1) * D];
#pragma unroll
                for (int cp = 0; cp < 16; cp++) {
                    ulonglong2 va = v0[cp];
                    ulonglong2 vb = v1[cp];
                    o2[2 * cp]     = ffma2(pa, va.x, o2[2 * cp]);
                    o2[2 * cp + 1] = ffma2(pa, va.y, o2[2 * cp + 1]);
                    o2[2 * cp]     = ffma2(pb, vb.x, o2[2 * cp]);
                    o2[2 * cp + 1] = ffma2(pb, vb.y, o2[2 * cp + 1]);
                }
            }
        }
    }

    float inv_l = 1.0f / l_run;
    int bb = bh >> 4, hh = bh & 15;
    float* dst = Oout + (size_t)(bb * S + q0 + t) * E + hh * D;
#pragma unroll
    for (int cp = 0; cp < 16; cp++) {
        float x0, x1, x2, x3;
        upk2(o2[2 * cp], x0, x1);
        upk2(o2[2 * cp + 1], x2, x3);
        float4 o4 = { x0 * inv_l, x1 * inv_l, x2 * inv_l, x3 * inv_l };
        *(float4*)&dst[cp * 4] = o4;
    }
}

// ---------------------------------------------------------------------------
extern "C" void kernel_launch(void* const* d_in, const int* in_sizes, int n_in,
                              void* d_out, int out_size)
{
    const float* query = (const float*)d_in[0];
    const float* key   = (const float*)d_in[1];
    const float* value = (const float*)d_in[2];
    const float* Wq    = (const float*)d_in[3];
    const float* bq    = (const float*)d_in[4];
    const float* Wk    = (const float*)d_in[5];
    const float* bk    = (const float*)d_in[6];
    const float* Wv    = (const float*)d_in[7];
    const float* bv    = (const float*)d_in[8];
    const float* Wo    = (const float*)d_in[9];
    const float* bo    = (const float*)d_in[10];

    void *pq, *pk, *pv, *patt;
    cudaGetSymbolAddress(&pq, g_q);
    cudaGetSymbolAddress(&pk, g_k);
    cudaGetSymbolAddress(&pv, g_v);
    cudaGetSymbolAddress(&patt, g_att);

    cudaFuncSetAttribute(attn_kernel, cudaFuncAttributeMaxDynamicSharedMemorySize,
                         ATTN_SMEM);

    dim3 pgrid(8, 32, 3);
    gemm_proj<<<pgrid, 256>>>(query, key, value, Wq, Wk, Wv, bq, bk, bv,
                              (float*)pq, (float*)pk, (float*)pv);

    dim3 agrid(S / BQ, B * H);  // (16, 32)
    attn_kernel<<<agrid, 128, ATTN_SMEM>>>((const float*)pq, (const float*)pk,
                                           (const float*)pv, (float*)patt);

    dim3 ggrid(8, 32);
    gemm_out<<<ggrid, 256>>>((const float*)patt, Wo, bo, (float*)d_out);
}

// round 15
// speedup vs baseline: 1.1757x; 1.1757x over previous
#include <cuda_runtime.h>
#include <cstdint>

// ===========================================================================
// MHA B=2,S=2048,E=1024,H=16,D=64 fp32.  SIMT f32x2 everywhere.
//  - GEMMs: R5 engine + launch_bounds(256,2) (562us proj / 190us out, x4).
//  - attention: R5 hot loop VERBATIM (1 row/thread, BQ=128, dup-q scalar x
//    transposed-K pairs, group-16 online softmax), UNCAPPED regs, plus only
//    peripheral slot cuts: QSTR=68 with float4 Q loads (aligned), float4
//    K/V tile loads (K transpose via scalar STS).
//  Proven dead ends: reg caps <200 (spill), 2-row/thread, key-split,
//  pair-split, k-packed scores, dup-A gemm smem.
// ===========================================================================

typedef unsigned long long ull;
#define DI __device__ __forceinline__

DI ull pk2(float lo, float hi) {
    ull r; asm("mov.b64 %0, {%1,%2};" : "=l"(r) : "f"(lo), "f"(hi)); return r;
}
DI void upk2(ull v, float& lo, float& hi) {
    asm("mov.b64 {%0,%1}, %2;" : "=f"(lo), "=f"(hi) : "l"(v));
}
DI ull ffma2(ull a, ull b, ull c) {
    ull d; asm("fma.rn.f32x2 %0, %1, %2, %3;" : "=l"(d) : "l"(a), "l"(b), "l"(c)); return d;
}
DI ull fmul2(ull a, ull b) {
    ull d; asm("mul.rn.f32x2 %0, %1, %2;" : "=l"(d) : "l"(a), "l"(b)); return d;
}

constexpr int B = 2, S = 2048, E = 1024, H = 16, D = 64;

__device__ float g_q[B * H * S * D];
__device__ float g_k[B * H * S * D];
__device__ float g_v[B * H * S * D];
__device__ float g_att[B * S * E];

// ---------------------------------------------------------------------------
// R5 GEMM engine with launch_bounds(256,2) (measured best).
// ---------------------------------------------------------------------------
template <int MODE>
DI void gemm_body(const float* __restrict__ X, const float* __restrict__ W,
                  const float* __restrict__ bias, float* __restrict__ out)
{
    __shared__ __align__(16) float As[8][132];
    __shared__ __align__(16) float Ws[8][132];

    const int tid = threadIdx.x;
    const int tx = tid & 15, ty = tid >> 4;
    const int m0 = blockIdx.y * 128;
    const int n0 = blockIdx.x * 128;
    const int lr = tid >> 1;
    const int lc = (tid & 1) << 2;

    const float* Xp = X + (size_t)(m0 + lr) * 1024 + lc;
    const float* Wp = W + (size_t)(n0 + lr) * 1024 + lc;

    ull acc[8][4];
#pragma unroll
    for (int i = 0; i < 8; i++)
#pragma unroll
        for (int j = 0; j < 4; j++) acc[i][j] = 0ull;

    float4 av = *(const float4*)Xp;
    float4 wv = *(const float4*)Wp;

    for (int k0 = 0; k0 < 1024; k0 += 8) {
        __syncthreads();
        As[lc + 0][lr] = av.x; As[lc + 1][lr] = av.y;
        As[lc + 2][lr] = av.z; As[lc + 3][lr] = av.w;
        Ws[lc + 0][lr] = wv.x; Ws[lc + 1][lr] = wv.y;
        Ws[lc + 2][lr] = wv.z; Ws[lc + 3][lr] = wv.w;
        __syncthreads();
        if (k0 + 8 < 1024) {
            av = *(const float4*)(Xp + k0 + 8);
            wv = *(const float4*)(Wp + k0 + 8);
        }
#pragma unroll
        for (int kk = 0; kk < 8; kk++) {
            float4 a0 = *(const float4*)&As[kk][ty * 4];
            float4 a1 = *(const float4*)&As[kk][64 + ty * 4];
            ulonglong2 b0 = *(const ulonglong2*)&Ws[kk][tx * 4];
            ulonglong2 b1 = *(const ulonglong2*)&Ws[kk][64 + tx * 4];
            float a[8] = {a0.x, a0.y, a0.z, a0.w, a1.x, a1.y, a1.z, a1.w};
            ull bv[4] = {b0.x, b0.y, b1.x, b1.y};
#pragma unroll
            for (int i = 0; i < 8; i++) {
                ull a2 = pk2(a[i], a[i]);
#pragma unroll
                for (int j = 0; j < 4; j++) acc[i][j] = ffma2(a2, bv[j], acc[i][j]);
            }
        }
    }

    float4 bias0 = *(const float4*)&bias[n0 + tx * 4];
    float4 bias1 = *(const float4*)&bias[n0 + 64 + tx * 4];

#pragma unroll
    for (int i = 0; i < 8; i++) {
        int m = m0 + (i >> 2) * 64 + ty * 4 + (i & 3);
        float4 r0, r1;
        upk2(acc[i][0], r0.x, r0.y); upk2(acc[i][1], r0.z, r0.w);
        upk2(acc[i][2], r1.x, r1.y); upk2(acc[i][3], r1.z, r1.w);
        r0.x += bias0.x; r0.y += bias0.y; r0.z += bias0.z; r0.w += bias0.w;
        r1.x += bias1.x; r1.y += bias1.y; r1.z += bias1.z; r1.w += bias1.w;
        if (MODE == 0) {
            int bb = m >> 11, ss = m & 2047;
            int nA = n0 + tx * 4;
            int nB = n0 + 64 + tx * 4;
            int hA = nA >> 6, dA = nA & 63;
            int hB = nB >> 6, dB = nB & 63;
            *(float4*)&out[((size_t)(bb * H + hA) * S + ss) * D + dA] = r0;
            *(float4*)&out[((size_t)(bb * H + hB) * S + ss) * D + dB] = r1;
        } else {
            *(float4*)&out[(size_t)m * 1024 + n0 + tx * 4] = r0;
            *(float4*)&out[(size_t)m * 1024 + n0 + 64 + tx * 4] = r1;
        }
    }
}

__global__ __launch_bounds__(256, 2) void gemm_proj(const float* __restrict__ xq,
                                                    const float* __restrict__ xk,
                                                    const float* __restrict__ xv,
                                                    const float* __restrict__ Wq,
                                                    const float* __restrict__ Wk,
                                                    const float* __restrict__ Wv,
                                                    const float* __restrict__ bq,
                                                    const float* __restrict__ bk,
                                                    const float* __restrict__ bv,
                                                    float* __restrict__ oq,
                                                    float* __restrict__ ok,
                                                    float* __restrict__ ov)
{
    const int z = blockIdx.z;
    const float* X = (z == 0) ? xq : (z == 1) ? xk : xv;
    const float* W = (z == 0) ? Wq : (z == 1) ? Wk : Wv;
    const float* bb = (z == 0) ? bq : (z == 1) ? bk : bv;
    float* out = (z == 0) ? oq : (z == 1) ? ok : ov;
    gemm_body<0>(X, W, bb, out);
}

__global__ __launch_bounds__(256, 2) void gemm_out(const float* __restrict__ X,
                                                   const float* __restrict__ W,
                                                   const float* __restrict__ bias,
                                                   float* __restrict__ out)
{
    gemm_body<1>(X, W, bias, out);
}

// ---------------------------------------------------------------------------
// R5 flash attention, uncapped, with vectorized periphery.
// BQ=128, 128 threads, 1 row/thread. Q stride 68 (aligned float4 reads).
// K transposed [d][68] (scores: dup-q scalar x key-pairs, broadcast reads);
// V row-major [j][64]. Group-wise online softmax (16 keys/group).
// ---------------------------------------------------------------------------
constexpr int BQ = 128, TK = 64;
constexpr int QSTR = 68, KSTR = 68;
constexpr int ATTN_SMEM = (BQ * QSTR + D * KSTR + TK * D) * 4;  // 68608

__global__ __launch_bounds__(128) void attn_kernel(const float* __restrict__ Q,
                                                   const float* __restrict__ K,
                                                   const float* __restrict__ V,
                                                   float* __restrict__ Oout)
{
    extern __shared__ float sm[];
    float* Qs  = sm;                  // [128][68]
    float* Kst = sm + BQ * QSTR;      // [64 d][68 keys]
    float* Vs  = Kst + D * KSTR;      // [64 keys][64 d]

    const int t  = threadIdx.x;
    const int bh = blockIdx.y;
    const int q0 = blockIdx.x * BQ;
    const float* Qb = Q + (size_t)bh * (S * D);
    const float* Kb = K + (size_t)bh * (S * D);
    const float* Vb = V + (size_t)bh * (S * D);

    // Q tile load: float4 LDG -> float4 STS (stride 68, aligned)
#pragma unroll
    for (int i = 0; i < 16; i++) {
        int idx = i * 128 + t;            // 0..2047 float4s
        int r = idx >> 4, c4 = idx & 15;
        float4 v = *(const float4*)&Qb[(size_t)(q0 + r) * D + c4 * 4];
        float4 sv = { v.x * 0.125f, v.y * 0.125f, v.z * 0.125f, v.w * 0.125f };
        *(float4*)&Qs[r * QSTR + c4 * 4] = sv;
    }

    ull o2[32];
#pragma unroll
    for (int i = 0; i < 32; i++) o2[i] = 0ull;
    float m_run = -3.0e38f, l_run = 0.0f;

    const float* qrow = &Qs[t * QSTR];

    for (int kt = 0; kt < S; kt += TK) {
        __syncthreads();
        // K: float4 LDG + scalar STS transpose; V: float4 both sides
#pragma unroll
        for (int i = 0; i < 8; i++) {
            int idx = i * 128 + t;            // 0..1023 float4s
            int j = idx >> 4, d4 = idx & 15;
            float4 kv = *(const float4*)&Kb[(size_t)(kt + j) * D + d4 * 4];
            Kst[(d4 * 4 + 0) * KSTR + j] = kv.x;
            Kst[(d4 * 4 + 1) * KSTR + j] = kv.y;
            Kst[(d4 * 4 + 2) * KSTR + j] = kv.z;
            Kst[(d4 * 4 + 3) * KSTR + j] = kv.w;
            *(float4*)&Vs[j * D + d4 * 4] =
                *(const float4*)&Vb[(size_t)(kt + j) * D + d4 * 4];
        }
        __syncthreads();

#pragma unroll
        for (int g = 0; g < 4; g++) {
            ull s2[8];
#pragma unroll
            for (int i = 0; i < 8; i++) s2[i] = 0ull;

#pragma unroll
            for (int dc = 0; dc < D; dc += 16) {
                float qf[16];
#pragma unroll
                for (int u = 0; u < 4; u++)
                    *(float4*)&qf[4 * u] = *(const float4*)&qrow[dc + 4 * u];
#pragma unroll
                for (int dd = 0; dd < 16; dd++) {
                    ull q2 = pk2(qf[dd], qf[dd]);
                    const ulonglong2* kr =
                        (const ulonglong2*)&Kst[(dc + dd) * KSTR + g * 16];
#pragma unroll
                    for (int u = 0; u < 4; u++) {
                        ulonglong2 kv = kr[u];
                        s2[2 * u]     = ffma2(q2, kv.x, s2[2 * u]);
                        s2[2 * u + 1] = ffma2(q2, kv.y, s2[2 * u + 1]);
                    }
                }
            }

            float gmax = -3.0e38f;
#pragma unroll
            for (int i = 0; i < 8; i++) {
                float x, y; upk2(s2[i], x, y);
                gmax = fmaxf(gmax, fmaxf(x, y));
            }
            if (__any_sync(0xffffffffu, gmax > m_run)) {
                float mnew = fmaxf(m_run, gmax);
                float alpha = __expf(m_run - mnew);
                l_run *= alpha;
                ull al2 = pk2(alpha, alpha);
#pragma unroll
                for (int i = 0; i < 32; i++) o2[i] = fmul2(o2[i], al2);
                m_run = mnew;
            }
            float lsum = 0.0f;
#pragma unroll
            for (int i = 0; i < 8; i++) {
                float x, y; upk2(s2[i], x, y);
                float p0 = __expf(x - m_run), p1 = __expf(y - m_run);
                lsum += p0 + p1;
                s2[i] = pk2(p0, p1);
            }
            l_run += lsum;

#pragma unroll
            for (int j2 = 0; j2 < 8; j2++) {
                int j = g * 16 + 2 * j2;
                float p0, p1; upk2(s2[j2], p0, p1);
                ull pa = pk2(p0, p0), pb = pk2(p1, p1);
                const ulonglong2* v0 = (const ulonglong2*)&Vs[j * D];
                const ulonglong2* v1 = (const ulonglong2*)&Vs[(j + 1) * D];
#pragma unroll
                for (int cp = 0; cp < 16; cp++) {
                    ulonglong2 va = v0[cp];
                    ulonglong2 vb = v1[cp];
                    o2[2 * cp]     = ffma2(pa, va.x, o2[2 * cp]);
                    o2[2 * cp + 1] = ffma2(pa, va.y, o2[2 * cp + 1]);
                    o2[2 * cp]     = ffma2(pb, vb.x, o2[2 * cp]);
                    o2[2 * cp + 1] = ffma2(pb, vb.y, o2[2 * cp + 1]);
                }
            }
        }
    }

    float inv_l = 1.0f / l_run;
    int bb = bh >> 4, hh = bh & 15;
    float* dst = Oout + (size_t)(bb * S + q0 + t) * E + hh * D;
#pragma unroll
    for (int cp = 0; cp < 16; cp++) {
        float x0, x1, x2, x3;
        upk2(o2[2 * cp], x0, x1);
        upk2(o2[2 * cp + 1], x2, x3);
        float4 o4 = { x0 * inv_l, x1 * inv_l, x2 * inv_l, x3 * inv_l };
        *(float4*)&dst[cp * 4] = o4;
    }
}

// ---------------------------------------------------------------------------
extern "C" void kernel_launch(void* const* d_in, const int* in_sizes, int n_in,
                              void* d_out, int out_size)
{
    const float* query = (const float*)d_in[0];
    const float* key   = (const float*)d_in[1];
    const float* value = (const float*)d_in[2];
    const float* Wq    = (const float*)d_in[3];
    const float* bq    = (const float*)d_in[4];
    const float* Wk    = (const float*)d_in[5];
    const float* bk    = (const float*)d_in[6];
    const float* Wv    = (const float*)d_in[7];
    const float* bv    = (const float*)d_in[8];
    const float* Wo    = (const float*)d_in[9];
    const float* bo    = (const float*)d_in[10];

    void *pq, *pk, *pv, *patt;
    cudaGetSymbolAddress(&pq, g_q);
    cudaGetSymbolAddress(&pk, g_k);
    cudaGetSymbolAddress(&pv, g_v);
    cudaGetSymbolAddress(&patt, g_att);

    cudaFuncSetAttribute(attn_kernel, cudaFuncAttributeMaxDynamicSharedMemorySize,
                         ATTN_SMEM);

    dim3 pgrid(8, 32, 3);
    gemm_proj<<<pgrid, 256>>>(query, key, value, Wq, Wk, Wv, bq, bk, bv,
                              (float*)pq, (float*)pk, (float*)pv);

    dim3 agrid(S / BQ, B * H);  // (16, 32)
    attn_kernel<<<agrid, 128, ATTN_SMEM>>>((const float*)pq, (const float*)pk,
                                           (const float*)pv, (float*)patt);

    dim3 ggrid(8, 32);
    gemm_out<<<ggrid, 256>>>((const float*)patt, Wo, bo, (float*)d_out);
}

// round 16
// speedup vs baseline: 1.1876x; 1.0101x over previous
#include <cuda_runtime.h>
#include <cstdint>

// ===========================================================================
// MHA B=2,S=2048,E=1024,H=16,D=64 fp32.  SIMT f32x2 everywhere.
//  - GEMMs: R5 inner loop + DOUBLE-BUFFERED smem (1 sync/chunk instead of 2,
//    STS overlapped with compute), launch_bounds(256,2).
//  - attention: R5 hot loop + DOUBLE-BUFFERED K/V tiles (next-K prefetched to
//    regs + next-V via cp.async during compute; 1 sync/tile), uncapped regs.
//  Proven dead ends: reg caps <200, 2-row/thread, key/pair-split, k-packed
//  scores, dup-A gemm smem, mma.sync (HMMA ~FFMA-rate here), tcgen05 (PTX
//  target lacks the 'a' feature suffix).
// ===========================================================================

typedef unsigned long long ull;
#define DI __device__ __forceinline__

DI ull pk2(float lo, float hi) {
    ull r; asm("mov.b64 %0, {%1,%2};" : "=l"(r) : "f"(lo), "f"(hi)); return r;
}
DI void upk2(ull v, float& lo, float& hi) {
    asm("mov.b64 {%0,%1}, %2;" : "=f"(lo), "=f"(hi) : "l"(v));
}
DI ull ffma2(ull a, ull b, ull c) {
    ull d; asm("fma.rn.f32x2 %0, %1, %2, %3;" : "=l"(d) : "l"(a), "l"(b), "l"(c)); return d;
}
DI ull fmul2(ull a, ull b) {
    ull d; asm("mul.rn.f32x2 %0, %1, %2;" : "=l"(d) : "l"(a), "l"(b)); return d;
}
DI uint32_t smem_u32(const void* p) {
    uint32_t a;
    asm("{ .reg .u64 t; cvta.to.shared.u64 t, %1; cvt.u32.u64 %0, t; }" : "=r"(a) : "l"(p));
    return a;
}
DI void cp_async16(uint32_t saddr, const void* gaddr) {
    asm volatile("cp.async.cg.shared.global [%0], [%1], 16;"
                 :: "r"(saddr), "l"(gaddr) : "memory");
}
DI void cp_commit() { asm volatile("cp.async.commit_group;" ::: "memory"); }
DI void cp_wait0()  { asm volatile("cp.async.wait_group 0;" ::: "memory"); }

constexpr int B = 2, S = 2048, E = 1024, H = 16, D = 64;

__device__ float g_q[B * H * S * D];
__device__ float g_k[B * H * S * D];
__device__ float g_v[B * H * S * D];
__device__ float g_att[B * S * E];

// ---------------------------------------------------------------------------
// GEMM: R5 inner loop, double-buffered smem, one sync per chunk.
// ---------------------------------------------------------------------------
template <int MODE>
DI void gemm_body(const float* __restrict__ X, const float* __restrict__ W,
                  const float* __restrict__ bias, float* __restrict__ out)
{
    __shared__ __align__(16) float As[2][8][132];
    __shared__ __align__(16) float Ws[2][8][132];

    const int tid = threadIdx.x;
    const int tx = tid & 15, ty = tid >> 4;
    const int m0 = blockIdx.y * 128;
    const int n0 = blockIdx.x * 128;
    const int lr = tid >> 1;
    const int lc = (tid & 1) << 2;

    const float* Xp = X + (size_t)(m0 + lr) * 1024 + lc;
    const float* Wp = W + (size_t)(n0 + lr) * 1024 + lc;

    ull acc[8][4];
#pragma unroll
    for (int i = 0; i < 8; i++)
#pragma unroll
        for (int j = 0; j < 4; j++) acc[i][j] = 0ull;

    // preload chunk 0, store to buf 0, prefetch chunk 1
    float4 av = *(const float4*)Xp;
    float4 wv = *(const float4*)Wp;
    As[0][lc + 0][lr] = av.x; As[0][lc + 1][lr] = av.y;
    As[0][lc + 2][lr] = av.z; As[0][lc + 3][lr] = av.w;
    Ws[0][lc + 0][lr] = wv.x; Ws[0][lc + 1][lr] = wv.y;
    Ws[0][lc + 2][lr] = wv.z; Ws[0][lc + 3][lr] = wv.w;
    av = *(const float4*)(Xp + 8);
    wv = *(const float4*)(Wp + 8);
    __syncthreads();

    for (int c = 0; c < 128; c++) {
        const int buf = c & 1;
        if (c + 1 < 128) {
            const int nb = buf ^ 1;
            As[nb][lc + 0][lr] = av.x; As[nb][lc + 1][lr] = av.y;
            As[nb][lc + 2][lr] = av.z; As[nb][lc + 3][lr] = av.w;
            Ws[nb][lc + 0][lr] = wv.x; Ws[nb][lc + 1][lr] = wv.y;
            Ws[nb][lc + 2][lr] = wv.z; Ws[nb][lc + 3][lr] = wv.w;
            if (c + 2 < 128) {
                av = *(const float4*)(Xp + (c + 2) * 8);
                wv = *(const float4*)(Wp + (c + 2) * 8);
            }
        }
#pragma unroll
        for (int kk = 0; kk < 8; kk++) {
            float4 a0 = *(const float4*)&As[buf][kk][ty * 4];
            float4 a1 = *(const float4*)&As[buf][kk][64 + ty * 4];
            ulonglong2 b0 = *(const ulonglong2*)&Ws[buf][kk][tx * 4];
            ulonglong2 b1 = *(const ulonglong2*)&Ws[buf][kk][64 + tx * 4];
            float a[8] = {a0.x, a0.y, a0.z, a0.w, a1.x, a1.y, a1.z, a1.w};
            ull bv[4] = {b0.x, b0.y, b1.x, b1.y};
#pragma unroll
            for (int i = 0; i < 8; i++) {
                ull a2 = pk2(a[i], a[i]);
#pragma unroll
                for (int j = 0; j < 4; j++) acc[i][j] = ffma2(a2, bv[j], acc[i][j]);
            }
        }
        __syncthreads();
    }

    float4 bias0 = *(const float4*)&bias[n0 + tx * 4];
    float4 bias1 = *(const float4*)&bias[n0 + 64 + tx * 4];

#pragma unroll
    for (int i = 0; i < 8; i++) {
        int m = m0 + (i >> 2) * 64 + ty * 4 + (i & 3);
        float4 r0, r1;
        upk2(acc[i][0], r0.x, r0.y); upk2(acc[i][1], r0.z, r0.w);
        upk2(acc[i][2], r1.x, r1.y); upk2(acc[i][3], r1.z, r1.w);
        r0.x += bias0.x; r0.y += bias0.y; r0.z += bias0.z; r0.w += bias0.w;
        r1.x += bias1.x; r1.y += bias1.y; r1.z += bias1.z; r1.w += bias1.w;
        if (MODE == 0) {
            int bb = m >> 11, ss = m & 2047;
            int nA = n0 + tx * 4;
            int nB = n0 + 64 + tx * 4;
            int hA = nA >> 6, dA = nA & 63;
            int hB = nB >> 6, dB = nB & 63;
            *(float4*)&out[((size_t)(bb * H + hA) * S + ss) * D + dA] = r0;
            *(float4*)&out[((size_t)(bb * H + hB) * S + ss) * D + dB] = r1;
        } else {
            *(float4*)&out[(size_t)m * 1024 + n0 + tx * 4] = r0;
            *(float4*)&out[(size_t)m * 1024 + n0 + 64 + tx * 4] = r1;
        }
    }
}

__global__ __launch_bounds__(256, 2) void gemm_proj(const float* __restrict__ xq,
                                                    const float* __restrict__ xk,
                                                    const float* __restrict__ xv,
                                                    const float* __restrict__ Wq,
                                                    const float* __restrict__ Wk,
                                                    const float* __restrict__ Wv,
                                                    const float* __restrict__ bq,
                                                    const float* __restrict__ bk,
                                                    const float* __restrict__ bv,
                                                    float* __restrict__ oq,
                                                    float* __restrict__ ok,
                                                    float* __restrict__ ov)
{
    const int z = blockIdx.z;
    const float* X = (z == 0) ? xq : (z == 1) ? xk : xv;
    const float* W = (z == 0) ? Wq : (z == 1) ? Wk : Wv;
    const float* bb = (z == 0) ? bq : (z == 1) ? bk : bv;
    float* out = (z == 0) ? oq : (z == 1) ? ok : ov;
    gemm_body<0>(X, W, bb, out);
}

__global__ __launch_bounds__(256, 2) void gemm_out(const float* __restrict__ X,
                                                   const float* __restrict__ W,
                                                   const float* __restrict__ bias,
                                                   float* __restrict__ out)
{
    gemm_body<1>(X, W, bias, out);
}

// ---------------------------------------------------------------------------
// Flash attention: R5 hot loop, double-buffered K/V tiles, 1 sync/tile.
// Next-K LDG into regs + next-V cp.async issued at tile start; STS of K and
// cp.wait at tile end (LDG latency hidden under ~6700 cyc of compute).
// ---------------------------------------------------------------------------
constexpr int BQ = 128, TK = 64;
constexpr int QSTR = 68, KSTR = 68;
// Q 128*68 + K 2*64*68 + V 2*64*64 = 25600 floats
constexpr int ATTN_SMEM = (BQ * QSTR + 2 * TK * KSTR + 2 * TK * D) * 4;  // 102400

__global__ __launch_bounds__(128) void attn_kernel(const float* __restrict__ Q,
                                                   const float* __restrict__ K,
                                                   const float* __restrict__ V,
                                                   float* __restrict__ Oout)
{
    extern __shared__ float sm[];
    float* Qs  = sm;                          // [128][68]
    float* Kst = sm + BQ * QSTR;              // [2][64][68] d-major
    float* Vs  = Kst + 2 * TK * KSTR;         // [2][64][64]

    const int t  = threadIdx.x;
    const int bh = blockIdx.y;
    const int q0 = blockIdx.x * BQ;
    const float* Qb = Q + (size_t)bh * (S * D);
    const float* Kb = K + (size_t)bh * (S * D);
    const float* Vb = V + (size_t)bh * (S * D);
    const uint32_t vs_base = smem_u32(Vs);

    // Q tile load
#pragma unroll
    for (int i = 0; i < 16; i++) {
        int idx = i * 128 + t;
        int r = idx >> 4, c4 = idx & 15;
        float4 v = *(const float4*)&Qb[(size_t)(q0 + r) * D + c4 * 4];
        float4 sv = { v.x * 0.125f, v.y * 0.125f, v.z * 0.125f, v.w * 0.125f };
        *(float4*)&Qs[r * QSTR + c4 * 4] = sv;
    }

    // per-thread K/V load coords: 8 float4 each
    int jj[8], dd4[8];
#pragma unroll
    for (int i = 0; i < 8; i++) {
        int idx = i * 128 + t;
        jj[i] = idx >> 4;
        dd4[i] = (idx & 15) * 4;
    }

    // preload tile 0 into buf 0
    {
        float4 kreg[8];
#pragma unroll
        for (int i = 0; i < 8; i++) {
            kreg[i] = *(const float4*)&Kb[(size_t)jj[i] * D + dd4[i]];
            cp_async16(vs_base + (uint32_t)(jj[i] * D + dd4[i]) * 4,
                       &Vb[(size_t)jj[i] * D + dd4[i]]);
        }
        cp_commit();
#pragma unroll
        for (int i = 0; i < 8; i++) {
            Kst[(dd4[i] + 0) * KSTR + jj[i]] = kreg[i].x;
            Kst[(dd4[i] + 1) * KSTR + jj[i]] = kreg[i].y;
            Kst[(dd4[i] + 2) * KSTR + jj[i]] = kreg[i].z;
            Kst[(dd4[i] + 3) * KSTR + jj[i]] = kreg[i].w;
        }
        cp_wait0();
    }
    __syncthreads();

    ull o2[32];
#pragma unroll
    for (int i = 0; i < 32; i++) o2[i] = 0ull;
    float m_run = -3.0e38f, l_run = 0.0f;

    const float* qrow = &Qs[t * QSTR];

    for (int kt_i = 0; kt_i < S / TK; kt_i++) {
        const int buf = kt_i & 1;
        const float* Kb_s = Kst + buf * (TK * KSTR);
        const float* Vb_s = Vs + buf * (TK * D);

        float4 kreg[8];
        if (kt_i + 1 < S / TK) {
            const float* Kn = Kb + (size_t)(kt_i + 1) * TK * D;
            const float* Vn = Vb + (size_t)(kt_i + 1) * TK * D;
            const uint32_t vdst = vs_base + (uint32_t)((buf ^ 1) * TK * D) * 4;
#pragma unroll
            for (int i = 0; i < 8; i++) {
                kreg[i] = *(const float4*)&Kn[(size_t)jj[i] * D + dd4[i]];
                cp_async16(vdst + (uint32_t)(jj[i] * D + dd4[i]) * 4,
                           &Vn[(size_t)jj[i] * D + dd4[i]]);
            }
            cp_commit();
        }

#pragma unroll
        for (int g = 0; g < 4; g++) {
            ull s2[8];
#pragma unroll
            for (int i = 0; i < 8; i++) s2[i] = 0ull;

#pragma unroll
            for (int dc = 0; dc < D; dc += 16) {
                float qf[16];
#pragma unroll
                for (int u = 0; u < 4; u++)
                    *(float4*)&qf[4 * u] = *(const float4*)&qrow[dc + 4 * u];
#pragma unroll
                for (int dd = 0; dd < 16; dd++) {
                    ull q2 = pk2(qf[dd], qf[dd]);
                    const ulonglong2* kr =
                        (const ulonglong2*)&Kb_s[(dc + dd) * KSTR + g * 16];
#pragma unroll
                    for (int u = 0; u < 4; u++) {
                        ulonglong2 kv = kr[u];
                        s2[2 * u]     = ffma2(q2, kv.x, s2[2 * u]);
                        s2[2 * u + 1] = ffma2(q2, kv.y, s2[2 * u + 1]);
                    }
                }
            }

            float gmax = -3.0e38f;
#pragma unroll
            for (int i = 0; i < 8; i++) {
                float x, y; upk2(s2[i], x, y);
                gmax = fmaxf(gmax, fmaxf(x, y));
            }
            if (__any_sync(0xffffffffu, gmax > m_run)) {
                float mnew = fmaxf(m_run, gmax);
                float alpha = __expf(m_run - mnew);
                l_run *= alpha;
                ull al2 = pk2(alpha, alpha);
#pragma unroll
                for (int i = 0; i < 32; i++) o2[i] = fmul2(o2[i], al2);
                m_run = mnew;
            }
            float lsum = 0.0f;
#pragma unroll
            for (int i = 0; i < 8; i++) {
                float x, y; upk2(s2[i], x, y);
                float p0 = __expf(x - m_run), p1 = __expf(y - m_run);
                lsum += p0 + p1;
                s2[i] = pk2(p0, p1);
            }
            l_run += lsum;

#pragma unroll
            for (int j2 = 0; j2 < 8; j2++) {
                int j = g * 16 + 2 * j2;
                float p0, p1; upk2(s2[j2], p0, p1);
                ull pa = pk2(p0, p0), pb = pk2(p1, p1);
                const ulonglong2* v0 = (const ulonglong2*)&Vb_s[j * D];
                const ulonglong2* v1 = (const ulonglong2*)&Vb_s[(j + 1) * D];
#pragma unroll
                for (int cp = 0; cp < 16; cp++) {
                    ulonglong2 va = v0[cp];
                    ulonglong2 vb = v1[cp];
                    o2[2 * cp]     = ffma2(pa, va.x, o2[2 * cp]);
                    o2[2 * cp + 1] = ffma2(pa, va.y, o2[2 * cp + 1]);
                    o2[2 * cp]     = ffma2(pb, vb.x, o2[2 * cp]);
                    o2[2 * cp + 1] = ffma2(pb, vb.y, o2[2 * cp + 1]);
                }
            }
        }

        if (kt_i + 1 < S / TK) {
            float* Kd = Kst + (buf ^ 1) * (TK * KSTR);
#pragma unroll
            for (int i = 0; i < 8; i++) {
                Kd[(dd4[i] + 0) * KSTR + jj[i]] = kreg[i].x;
                Kd[(dd4[i] + 1) * KSTR + jj[i]] = kreg[i].y;
                Kd[(dd4[i] + 2) * KSTR + jj[i]] = kreg[i].z;
                Kd[(dd4[i] + 3) * KSTR + jj[i]] = kreg[i].w;
            }
            cp_wait0();
        }
        __syncthreads();
    }

    float inv_l = 1.0f / l_run;
    int bb = bh >> 4, hh = bh & 15;
    float* dst = Oout + (size_t)(bb * S + q0 + t) * E + hh * D;
#pragma unroll
    for (int cp = 0; cp < 16; cp++) {
        float x0, x1, x2, x3;
        upk2(o2[2 * cp], x0, x1);
        upk2(o2[2 * cp + 1], x2, x3);
        float4 o4 = { x0 * inv_l, x1 * inv_l, x2 * inv_l, x3 * inv_l };
        *(float4*)&dst[cp * 4] = o4;
    }
}

// ---------------------------------------------------------------------------
extern "C" void kernel_launch(void* const* d_in, const int* in_sizes, int n_in,
                              void* d_out, int out_size)
{
    const float* query = (const float*)d_in[0];
    const float* key   = (const float*)d_in[1];
    const float* value = (const float*)d_in[2];
    const float* Wq    = (const float*)d_in[3];
    const float* bq    = (const float*)d_in[4];
    const float* Wk    = (const float*)d_in[5];
    const float* bk    = (const float*)d_in[6];
    const float* Wv    = (const float*)d_in[7];
    const float* bv    = (const float*)d_in[8];
    const float* Wo    = (const float*)d_in[9];
    const float* bo    = (const float*)d_in[10];

    void *pq, *pk, *pv, *patt;
    cudaGetSymbolAddress(&pq, g_q);
    cudaGetSymbolAddress(&pk, g_k);
    cudaGetSymbolAddress(&pv, g_v);
    cudaGetSymbolAddress(&patt, g_att);

    cudaFuncSetAttribute(attn_kernel, cudaFuncAttributeMaxDynamicSharedMemorySize,
                         ATTN_SMEM);

    dim3 pgrid(8, 32, 3);
    gemm_proj<<<pgrid, 256>>>(query, key, value, Wq, Wk, Wv, bq, bk, bv,
                              (float*)pq, (float*)pk, (float*)pv);

    dim3 agrid(S / BQ, B * H);  // (16, 32)
    attn_kernel<<<agrid, 128, ATTN_SMEM>>>((const float*)pq, (const float*)pk,
                                           (const float*)pv, (float*)patt);

    dim3 ggrid(8, 32);
    gemm_out<<<ggrid, 256>>>((const float*)patt, Wo, bo, (float*)d_out);
}